// round 14
// baseline (speedup 1.0000x reference)
#include <cuda_runtime.h>
#include <cuda_fp16.h>
#include <cstdint>

// Problem constants
#define N_ROWS 8192
#define HDIM   1024
#define B0DIM  64
#define FDIM   2048
#define ODIM   2048
#define XDIM   (HDIM + B0DIM + FDIM)   // 3136
#define NB     6

#define BM 128
#define BN 128
#define BK 64

// smem: rows are 128B (64 fp16) = SW128 atom; seg-XOR swizzle:
// addr(row r, 16B-seg s) = r*128 + ((s ^ (r&7))<<4)
#define OFF_A    0
#define OFF_B    16384
#define SM_STAGE 32768
#define NSTG     3
#define SMEM_TOTAL (NSTG * SM_STAGE)   // 98304 -> 2 CTAs/SM

// weight arena element offsets (single fp16 plane)
#define NW_WS    (FDIM * FDIM)
#define NW_WSQ   (FDIM * HDIM)
#define NW_WH0Q  (FDIM * B0DIM)
#define NW_WH0H  (HDIM * B0DIM)
#define NW_WQ0H  (HDIM * FDIM)
#define NW_WOUT  (ODIM * FDIM)
#define NW_WAQ   (NB * FDIM * FDIM)
#define NW_WDH   (NB * HDIM * FDIM)
#define NW_WFH   (NB * HDIM * FDIM)
#define NW_WHF   (NB * FDIM * HDIM)
#define NW_WRESQ (NB * HDIM * FDIM)

#define O_WS    0
#define O_WSQ   (O_WS + NW_WS)
#define O_WH0Q  (O_WSQ + NW_WSQ)
#define O_WH0H  (O_WH0Q + NW_WH0Q)
#define O_WQ0H  (O_WH0H + NW_WH0H)
#define O_WOUT  (O_WQ0H + NW_WQ0H)
#define O_WAQ   (O_WOUT + NW_WOUT)
#define O_WDH   (O_WAQ + NW_WAQ)
#define O_WFH   (O_WDH + NW_WDH)
#define O_WHF   (O_WFH + NW_WFH)
#define O_WRESQ (O_WHF + NW_WHF)
#define NW_TOT  (O_WRESQ + NW_WRESQ)

#define NX   (N_ROWS * XDIM)
#define NF   (N_ROWS * FDIM)
#define NH   (N_ROWS * HDIM)

// -------------------- scratch (device globals; no allocs allowed) ---------
__device__ float g_q   [NF];
__device__ float g_sumq[NF];
__device__ float g_rS  [NF];
__device__ float g_sumh[NH];
__device__ float g_rqh [NH];
__device__ float g_Dh  [NH];

__device__ unsigned short g_wh [NW_TOT];   // weights, fp16
__device__ unsigned short g_xh [NX];       // activations, fp16
__device__ unsigned short g_qh [NF];
__device__ unsigned short g_tbh[NF];       // A-operand of Aq GEMM
__device__ unsigned short g_tb2h[NF];      // A-operand of fh GEMM (ping-pong)
__device__ unsigned short g_aqh[NF];
__device__ unsigned short g_thh[NH];

// -------------------- helpers ---------------------------------------------
__device__ __forceinline__ uint32_t swz(int row, int seg)
{
    return (uint32_t)(row * 128 + ((seg ^ (row & 7)) << 4));
}

__device__ __forceinline__ void ldsm_x4(uint32_t& r0, uint32_t& r1,
                                        uint32_t& r2, uint32_t& r3,
                                        uint32_t addr)
{
    asm volatile("ldmatrix.sync.aligned.m8n8.x4.shared.b16 {%0,%1,%2,%3}, [%4];"
                 : "=r"(r0), "=r"(r1), "=r"(r2), "=r"(r3) : "r"(addr));
}

__device__ __forceinline__ void mma16816(float* c, const uint32_t* a,
                                         uint32_t b0, uint32_t b1)
{
    asm volatile(
        "mma.sync.aligned.m16n8k16.row.col.f32.f16.f16.f32 "
        "{%0,%1,%2,%3}, {%4,%5,%6,%7}, {%8,%9}, {%0,%1,%2,%3};"
        : "+f"(c[0]), "+f"(c[1]), "+f"(c[2]), "+f"(c[3])
        : "r"(a[0]), "r"(a[1]), "r"(a[2]), "r"(a[3]), "r"(b0), "r"(b1));
}

__device__ __forceinline__ uint32_t packh2(float x, float y)
{
    __half hx = __float2half_rn(x);
    __half hy = __float2half_rn(y);
    return ((uint32_t)__half_as_ushort(hy) << 16) | __half_as_ushort(hx);
}

__device__ __forceinline__ void cpa16(uint32_t dst, const void* src)
{
    asm volatile("cp.async.cg.shared.global [%0], [%1], 16;"
                 :: "r"(dst), "l"(src) : "memory");
}
#define CPA_COMMIT() asm volatile("cp.async.commit_group;" ::: "memory")
#define CPA_WAIT(n)  asm volatile("cp.async.wait_group %0;" :: "n"(n) : "memory")

// -------------------- fp16 single-pass tensor GEMM (BK=64, 3 stages) ------
// v = A[M,K] @ W[Fout,K]^T + bias  (A, W both single fp16 planes)
// EPI 0: C = v
// EPI 1: C = relu(v)
// EPI 2: C += v
// EPI 3: q-update: q = C - leaky(v, a); C = q; Ch = fp16(q); Xh = fp16(q*P1)
// EPI 4: Ch = fp16(v); Xh = fp16(v*(P1+P2))            (no fp32 C write)
// EPI 5: h = relu(v); Xh = fp16((h+P1+P2)*P3)          (no fp32 C write)
template <int EPI>
__global__ __launch_bounds__(256, 2) void gemm_f16(
    const unsigned short* __restrict__ A, int lda,
    const unsigned short* __restrict__ W,        // ldw == K
    const float* __restrict__ bias,
    float* __restrict__ C,
    unsigned short* __restrict__ Ch,
    unsigned short* __restrict__ Xh, int ldc,
    int K,
    const float* __restrict__ P1,
    const float* __restrict__ P2,
    const float* __restrict__ P3,
    const float* __restrict__ a_ptr)
{
    extern __shared__ __align__(16) char smem[];
    const uint32_t sb = (uint32_t)__cvta_generic_to_shared(smem);

    const int t    = threadIdx.x;
    const int lane = t & 31;
    const int warp = t >> 5;
    const int wm   = warp >> 1;      // 0..3
    const int wn   = warp & 1;       // 0..1
    const int m0   = wm * 32;        // warp tile 32x64
    const int n0   = wn * 64;
    const int brow = blockIdx.y * BM;
    const int bcol = blockIdx.x * BN;

    // copy mapping: row = t>>1, col-half = (t&1)*32 elems = segs {4h..4h+3}
    const int crow = t >> 1;
    const int s0   = (t & 1) * 4;
    const size_t aIdx = (size_t)(brow + crow) * lda + (t & 1) * 32;
    const size_t bIdx = (size_t)(bcol + crow) * K   + (t & 1) * 32;
    uint32_t dA[4];
#pragma unroll
    for (int g = 0; g < 4; g++) dA[g] = swz(crow, s0 + g);

    float acc[2][8][4];
#pragma unroll
    for (int mt = 0; mt < 2; mt++)
#pragma unroll
        for (int nt = 0; nt < 8; nt++)
#pragma unroll
            for (int i = 0; i < 4; i++) acc[mt][nt][i] = 0.f;

    const int rA0    = m0 + (lane & 15);
    const int sAbase = lane >> 4;
    const int rB0    = n0 + (lane & 7) + ((lane >> 4) << 3);
    const int sBbase = (lane >> 3) & 1;

    const int nch = K / BK;

    // issue stage 0 (chunk 0)
    {
#pragma unroll
        for (int g = 0; g < 4; g++) {
            cpa16(sb + OFF_A + dA[g], A + aIdx + g * 8);
            cpa16(sb + OFF_B + dA[g], W + bIdx + g * 8);
        }
        CPA_COMMIT();
    }

    int stg = 0;
    for (int c = 0; c < nch; c++) {
        if (c + 1 < nch) {
            const int k1 = (c + 1) * BK;
            int stg1 = stg + 1; if (stg1 == NSTG) stg1 = 0;
            const uint32_t sd = sb + (uint32_t)stg1 * SM_STAGE;
#pragma unroll
            for (int g = 0; g < 4; g++) {
                cpa16(sd + OFF_A + dA[g], A + aIdx + k1 + g * 8);
                cpa16(sd + OFF_B + dA[g], W + bIdx + k1 + g * 8);
            }
            CPA_COMMIT();
            CPA_WAIT(1);
        } else {
            CPA_WAIT(0);
        }
        __syncthreads();   // single barrier per chunk (ring depth >= 3)

        const uint32_t stgb = sb + (uint32_t)stg * SM_STAGE;
#pragma unroll
        for (int kk = 0; kk < BK; kk += 16) {
            const int sA = sAbase + (kk >> 3);
            const int sB = sBbase + (kk >> 3);
            uint32_t b[4][4];
#pragma unroll
            for (int g = 0; g < 4; g++)
                ldsm_x4(b[g][0], b[g][1], b[g][2], b[g][3],
                        stgb + OFF_B + swz(rB0 + g * 16, sB));
            uint32_t a[2][4];
#pragma unroll
            for (int mt = 0; mt < 2; mt++)
                ldsm_x4(a[mt][0], a[mt][1], a[mt][2], a[mt][3],
                        stgb + OFF_A + swz(rA0 + mt * 16, sA));
#pragma unroll
            for (int mt = 0; mt < 2; mt++)
#pragma unroll
                for (int nt = 0; nt < 8; nt++)
                    mma16816(acc[mt][nt], a[mt],
                             b[nt >> 1][(nt & 1) * 2], b[nt >> 1][(nt & 1) * 2 + 1]);
        }
        if (++stg == NSTG) stg = 0;
    }

    // ---- epilogue ----
    const float alpha = (EPI == 3) ? a_ptr[0] : 0.f;
#pragma unroll
    for (int mt = 0; mt < 2; mt++) {
#pragma unroll
        for (int half = 0; half < 2; half++) {
            const int row  = brow + m0 + mt * 16 + (lane >> 2) + half * 8;
            const int col0 = bcol + n0 + (lane & 3) * 2;
            const size_t base = (size_t)row * ldc + col0;
            const float* brow_b = bias + col0;
#pragma unroll
            for (int nt = 0; nt < 8; nt++) {
                float v0 = acc[mt][nt][half * 2 + 0] + brow_b[nt * 8 + 0];
                float v1 = acc[mt][nt][half * 2 + 1] + brow_b[nt * 8 + 1];
                const size_t idx = base + nt * 8;
                if (EPI == 0) {
                    *(float2*)(C + idx) = make_float2(v0, v1);
                }
                if (EPI == 1) {
                    v0 = fmaxf(v0, 0.f); v1 = fmaxf(v1, 0.f);
                    *(float2*)(C + idx) = make_float2(v0, v1);
                }
                if (EPI == 2) {
                    float2 old = *(float2*)(C + idx);
                    *(float2*)(C + idx) = make_float2(old.x + v0, old.y + v1);
                }
                if (EPI == 3) {
                    float2 old = *(float2*)(C + idx);
                    float l0 = (v0 >= 0.f) ? v0 : alpha * v0;
                    float l1 = (v1 >= 0.f) ? v1 : alpha * v1;
                    float q0 = old.x - l0, q1 = old.y - l1;
                    *(float2*)(C + idx) = make_float2(q0, q1);
                    *(uint32_t*)(Ch + idx) = packh2(q0, q1);
                    float2 p1 = *(const float2*)(P1 + idx);
                    *(uint32_t*)(Xh + idx) = packh2(q0 * p1.x, q1 * p1.y);
                }
                if (EPI == 4) {
                    *(uint32_t*)(Ch + idx) = packh2(v0, v1);
                    float2 p1 = *(const float2*)(P1 + idx);
                    float2 p2 = *(const float2*)(P2 + idx);
                    *(uint32_t*)(Xh + idx) =
                        packh2(v0 * (p1.x + p2.x), v1 * (p1.y + p2.y));
                }
                if (EPI == 5) {
                    float h0 = fmaxf(v0, 0.f), h1 = fmaxf(v1, 0.f);
                    float2 p1 = *(const float2*)(P1 + idx);
                    float2 p2 = *(const float2*)(P2 + idx);
                    float2 p3 = *(const float2*)(P3 + idx);
                    *(uint32_t*)(Xh + idx) =
                        packh2((h0 + p1.x + p2.x) * p3.x,
                               (h1 + p1.y + p2.y) * p3.y);
                }
            }
        }
    }
}

// -------------------- converters & elementwise ----------------------------
__global__ __launch_bounds__(256) void k_cvt(const float* __restrict__ in,
                                             unsigned short* __restrict__ h,
                                             int n4)
{
    const int i = blockIdx.x * blockDim.x + threadIdx.x;
    if (i >= n4) return;
    float4 v = ((const float4*)in)[i];
    ((uint2*)h)[i] = make_uint2(packh2(v.x, v.y), packh2(v.z, v.w));
}

// q = (pi/4)*d^2 ; writes q fp32, qh fp16, tbh = fp16(q*rS)
__global__ __launch_bounds__(256) void k_square(const float* __restrict__ x,
                                                const float* __restrict__ rS,
                                                float* __restrict__ q,
                                                unsigned short* __restrict__ qh,
                                                unsigned short* __restrict__ tbh)
{
    const int i = blockIdx.x * blockDim.x + threadIdx.x;
    const int row = i / (FDIM / 4);
    const int c4  = i % (FDIM / 4);
    const float4 d = *(const float4*)(x + (size_t)row * XDIM + HDIM + B0DIM + c4 * 4);
    const float s = 0.78539816339744830962f;
    float4 o;
    o.x = s * d.x * d.x; o.y = s * d.y * d.y;
    o.z = s * d.z * d.z; o.w = s * d.w * d.w;
    const int oi = row * (FDIM / 4) + c4;
    ((float4*)q)[oi] = o;
    ((uint2*)qh)[oi] = make_uint2(packh2(o.x, o.y), packh2(o.z, o.w));
    const float4 r = ((const float4*)rS)[oi];
    ((uint2*)tbh)[oi] = make_uint2(packh2(o.x * r.x, o.y * r.y),
                                   packh2(o.z * r.z, o.w * r.w));
}

// -------------------- driver ----------------------------------------------
extern "C" void kernel_launch(void* const* d_in, const int* in_sizes, int n_in,
                              void* d_out, int out_size)
{
    const float* x      = (const float*)d_in[0];
    const float* W_h0q  = (const float*)d_in[1];
    const float* b_h0q  = (const float*)d_in[2];
    const float* W_sq   = (const float*)d_in[3];
    const float* b_sq   = (const float*)d_in[4];
    const float* W_h0h  = (const float*)d_in[5];
    const float* b_h0h  = (const float*)d_in[6];
    const float* W_S    = (const float*)d_in[7];
    const float* b_S    = (const float*)d_in[8];
    const float* W_q0h  = (const float*)d_in[9];
    const float* b_q0h  = (const float*)d_in[10];
    const float* Wb_Aq  = (const float*)d_in[11];
    const float* bb_Aq  = (const float*)d_in[12];
    const float* Wb_Dh  = (const float*)d_in[13];
    const float* bb_Dh  = (const float*)d_in[14];
    const float* Wb_fh  = (const float*)d_in[15];
    const float* bb_fh  = (const float*)d_in[16];
    const float* Wb_hf  = (const float*)d_in[17];
    const float* bb_hf  = (const float*)d_in[18];
    const float* a_hf   = (const float*)d_in[19];
    const float* Wb_resq= (const float*)d_in[20];
    const float* bb_resq= (const float*)d_in[21];
    const float* W_out  = (const float*)d_in[22];
    const float* b_out  = (const float*)d_in[23];

    float *q, *sumq, *rS, *sumh, *rqh, *Dh;
    cudaGetSymbolAddress((void**)&q,    g_q);
    cudaGetSymbolAddress((void**)&sumq, g_sumq);
    cudaGetSymbolAddress((void**)&rS,   g_rS);
    cudaGetSymbolAddress((void**)&sumh, g_sumh);
    cudaGetSymbolAddress((void**)&rqh,  g_rqh);
    cudaGetSymbolAddress((void**)&Dh,   g_Dh);

    unsigned short *wh, *xh, *qh, *tbh, *tb2h, *aqh, *thh;
    cudaGetSymbolAddress((void**)&wh,   g_wh);
    cudaGetSymbolAddress((void**)&xh,   g_xh);
    cudaGetSymbolAddress((void**)&qh,   g_qh);
    cudaGetSymbolAddress((void**)&tbh,  g_tbh);
    cudaGetSymbolAddress((void**)&tb2h, g_tb2h);
    cudaGetSymbolAddress((void**)&aqh,  g_aqh);
    cudaGetSymbolAddress((void**)&thh,  g_thh);

    cudaFuncSetAttribute(gemm_f16<0>, cudaFuncAttributeMaxDynamicSharedMemorySize, SMEM_TOTAL);
    cudaFuncSetAttribute(gemm_f16<1>, cudaFuncAttributeMaxDynamicSharedMemorySize, SMEM_TOTAL);
    cudaFuncSetAttribute(gemm_f16<2>, cudaFuncAttributeMaxDynamicSharedMemorySize, SMEM_TOTAL);
    cudaFuncSetAttribute(gemm_f16<3>, cudaFuncAttributeMaxDynamicSharedMemorySize, SMEM_TOTAL);
    cudaFuncSetAttribute(gemm_f16<4>, cudaFuncAttributeMaxDynamicSharedMemorySize, SMEM_TOTAL);
    cudaFuncSetAttribute(gemm_f16<5>, cudaFuncAttributeMaxDynamicSharedMemorySize, SMEM_TOTAL);

    // ---- one-time weight + x conversion to fp16 ----
    auto CVT = [&](const float* src, unsigned short* dst, int n) {
        const int n4 = n / 4;
        k_cvt<<<(n4 + 255) / 256, 256>>>(src, dst, n4);
    };
    CVT(W_S,    wh + O_WS,    NW_WS);
    CVT(W_sq,   wh + O_WSQ,   NW_WSQ);
    CVT(W_h0q,  wh + O_WH0Q,  NW_WH0Q);
    CVT(W_h0h,  wh + O_WH0H,  NW_WH0H);
    CVT(W_q0h,  wh + O_WQ0H,  NW_WQ0H);
    CVT(W_out,  wh + O_WOUT,  NW_WOUT);
    CVT(Wb_Aq,  wh + O_WAQ,   NW_WAQ);
    CVT(Wb_Dh,  wh + O_WDH,   NW_WDH);
    CVT(Wb_fh,  wh + O_WFH,   NW_WFH);
    CVT(Wb_hf,  wh + O_WHF,   NW_WHF);
    CVT(Wb_resq,wh + O_WRESQ, NW_WRESQ);
    CVT(x,      xh,           NX);

    const dim3 gF(FDIM / BN, N_ROWS / BM);   // (16, 64)
    const dim3 gH(HDIM / BN, N_ROWS / BM);   // (8, 64)
    const int ewF = (N_ROWS * FDIM / 4) / 256;

    // ---- prologue ----
    gemm_f16<0><<<gF, 256, SMEM_TOTAL>>>(xh + HDIM, XDIM, wh + O_WH0Q, b_h0q,
        sumq, nullptr, nullptr, FDIM, B0DIM, nullptr, nullptr, nullptr, nullptr);
    gemm_f16<2><<<gF, 256, SMEM_TOTAL>>>(xh, XDIM, wh + O_WSQ, b_sq,
        sumq, nullptr, nullptr, FDIM, HDIM, nullptr, nullptr, nullptr, nullptr);
    gemm_f16<0><<<gH, 256, SMEM_TOTAL>>>(xh + HDIM, XDIM, wh + O_WH0H, b_h0h,
        sumh, nullptr, nullptr, HDIM, B0DIM, nullptr, nullptr, nullptr, nullptr);
    gemm_f16<1><<<gF, 256, SMEM_TOTAL>>>(xh + HDIM + B0DIM, XDIM, wh + O_WS, b_S,
        rS, nullptr, nullptr, FDIM, FDIM, nullptr, nullptr, nullptr, nullptr);
    k_square<<<ewF, 256>>>(x, rS, q, qh, tbh);
    gemm_f16<0><<<gH, 256, SMEM_TOTAL>>>(qh, FDIM, wh + O_WQ0H, b_q0h,
        rqh, nullptr, nullptr, HDIM, FDIM, nullptr, nullptr, nullptr, nullptr);

    // ---- 6 unrolled blocks (5 GEMMs each, all elementwise fused) ----
    for (int nb = 0; nb < NB; nb++) {
        const size_t oAq   = O_WAQ   + (size_t)nb * FDIM * FDIM;
        const size_t oDh   = O_WDH   + (size_t)nb * HDIM * FDIM;
        const size_t oFh   = O_WFH   + (size_t)nb * HDIM * FDIM;
        const size_t oHf   = O_WHF   + (size_t)nb * FDIM * HDIM;
        const size_t oResq = O_WRESQ + (size_t)nb * HDIM * FDIM;
        const float* bAq   = bb_Aq   + (size_t)nb * FDIM;
        const float* bDh   = bb_Dh   + (size_t)nb * HDIM;
        const float* bfh   = bb_fh   + (size_t)nb * HDIM;
        const float* bhf   = bb_hf   + (size_t)nb * FDIM;
        const float* bresq = bb_resq + (size_t)nb * HDIM;

        gemm_f16<4><<<gF, 256, SMEM_TOTAL>>>(tbh, FDIM, wh + oAq, bAq,
            nullptr, aqh, tb2h, FDIM, FDIM, q, sumq, nullptr, nullptr);
        gemm_f16<1><<<gH, 256, SMEM_TOTAL>>>(aqh, FDIM, wh + oDh, bDh,
            Dh, nullptr, nullptr, HDIM, FDIM, nullptr, nullptr, nullptr, nullptr);
        gemm_f16<5><<<gH, 256, SMEM_TOTAL>>>(tb2h, FDIM, wh + oFh, bfh,
            nullptr, nullptr, thh, HDIM, FDIM, sumh, rqh, Dh, nullptr);
        gemm_f16<3><<<gF, 256, SMEM_TOTAL>>>(thh, HDIM, wh + oHf, bhf,
            q, qh, tbh, FDIM, HDIM, rS, nullptr, nullptr, a_hf + nb);
        gemm_f16<1><<<gH, 256, SMEM_TOTAL>>>(qh, FDIM, wh + oResq, bresq,
            rqh, nullptr, nullptr, HDIM, FDIM, nullptr, nullptr, nullptr, nullptr);
    }

    // ---- output ----
    gemm_f16<0><<<gF, 256, SMEM_TOTAL>>>(qh, FDIM, wh + O_WOUT, b_out,
        (float*)d_out, nullptr, nullptr, ODIM, FDIM, nullptr, nullptr, nullptr, nullptr);
}

// round 15
// speedup vs baseline: 1.0555x; 1.0555x over previous
#include <cuda_runtime.h>
#include <cuda_fp16.h>
#include <cstdint>

// Problem constants
#define N_ROWS 8192
#define HDIM   1024
#define B0DIM  64
#define FDIM   2048
#define ODIM   2048
#define XDIM   (HDIM + B0DIM + FDIM)   // 3136
#define NB     6

#define BM 128
#define BN 128
#define BK 32

// smem: rows are exactly 64B (32 fp16); segment-XOR swizzle kills conflicts.
#define OFF_A    0
#define OFF_B    8192
#define SM_STAGE 16384
#define NSTG     4
#define SMEM_TOTAL (NSTG * SM_STAGE)   // 65536 -> 2 CTAs/SM

// weight arena element offsets (single fp16 plane)
#define NW_WS    (FDIM * FDIM)
#define NW_WSQ   (FDIM * HDIM)
#define NW_WH0Q  (FDIM * B0DIM)
#define NW_WH0H  (HDIM * B0DIM)
#define NW_WQ0H  (HDIM * FDIM)
#define NW_WOUT  (ODIM * FDIM)
#define NW_WAQ   (NB * FDIM * FDIM)
#define NW_WDH   (NB * HDIM * FDIM)
#define NW_WFH   (NB * HDIM * FDIM)
#define NW_WHF   (NB * FDIM * HDIM)
#define NW_WRESQ (NB * HDIM * FDIM)

#define O_WS    0
#define O_WSQ   (O_WS + NW_WS)
#define O_WH0Q  (O_WSQ + NW_WSQ)
#define O_WH0H  (O_WH0Q + NW_WH0Q)
#define O_WQ0H  (O_WH0H + NW_WH0H)
#define O_WOUT  (O_WQ0H + NW_WQ0H)
#define O_WAQ   (O_WOUT + NW_WOUT)
#define O_WDH   (O_WAQ + NW_WAQ)
#define O_WFH   (O_WDH + NW_WDH)
#define O_WHF   (O_WFH + NW_WFH)
#define O_WRESQ (O_WHF + NW_WHF)
#define NW_TOT  (O_WRESQ + NW_WRESQ)

#define NX   (N_ROWS * XDIM)
#define NF   (N_ROWS * FDIM)
#define NH   (N_ROWS * HDIM)

// -------------------- scratch (device globals; no allocs allowed) ---------
__device__ float g_q   [NF];
__device__ float g_sumq[NF];
__device__ float g_rS  [NF];
__device__ float g_sumh[NH];
__device__ float g_rqh [NH];
__device__ float g_Dh  [NH];

__device__ unsigned short g_wh [NW_TOT];   // weights, fp16
__device__ unsigned short g_xh [NX];       // activations, fp16
__device__ unsigned short g_qh [NF];
__device__ unsigned short g_tbh[NF];       // A-operand of Aq GEMM
__device__ unsigned short g_tb2h[NF];      // A-operand of fh GEMM (ping-pong)
__device__ unsigned short g_aqh[NF];
__device__ unsigned short g_thh[NH];

// -------------------- helpers ---------------------------------------------
__device__ __forceinline__ uint32_t swz(int row, int seg)
{
    return (uint32_t)(row * 64 + ((seg ^ ((row >> 1) & 3)) << 4));
}

__device__ __forceinline__ void ldsm_x4(uint32_t& r0, uint32_t& r1,
                                        uint32_t& r2, uint32_t& r3,
                                        uint32_t addr)
{
    asm volatile("ldmatrix.sync.aligned.m8n8.x4.shared.b16 {%0,%1,%2,%3}, [%4];"
                 : "=r"(r0), "=r"(r1), "=r"(r2), "=r"(r3) : "r"(addr));
}

__device__ __forceinline__ void mma16816(float* c, const uint32_t* a,
                                         uint32_t b0, uint32_t b1)
{
    asm volatile(
        "mma.sync.aligned.m16n8k16.row.col.f32.f16.f16.f32 "
        "{%0,%1,%2,%3}, {%4,%5,%6,%7}, {%8,%9}, {%0,%1,%2,%3};"
        : "+f"(c[0]), "+f"(c[1]), "+f"(c[2]), "+f"(c[3])
        : "r"(a[0]), "r"(a[1]), "r"(a[2]), "r"(a[3]), "r"(b0), "r"(b1));
}

__device__ __forceinline__ uint32_t packh2(float x, float y)
{
    __half hx = __float2half_rn(x);
    __half hy = __float2half_rn(y);
    return ((uint32_t)__half_as_ushort(hy) << 16) | __half_as_ushort(hx);
}

__device__ __forceinline__ void cpa16(uint32_t dst, const void* src)
{
    asm volatile("cp.async.cg.shared.global [%0], [%1], 16;"
                 :: "r"(dst), "l"(src) : "memory");
}
#define CPA_COMMIT() asm volatile("cp.async.commit_group;" ::: "memory")
#define CPA_WAIT(n)  asm volatile("cp.async.wait_group %0;" :: "n"(n) : "memory")

// -------------------- fp16 single-pass tensor GEMM (4-stage pipeline) -----
// v = A[M,K] @ W[Fout,K]^T + bias  (A, W both single fp16 planes)
// EPI 0: C = v
// EPI 1: C = relu(v)
// EPI 2: C += v
// EPI 3: q-update: q = C - leaky(v, a); C = q; Ch = fp16(q); Xh = fp16(q*P1)
// EPI 4: Ch = fp16(v); Xh = fp16(v*(P1+P2))            (no fp32 C write)
// EPI 5: h = relu(v); Xh = fp16((h+P1+P2)*P3)          (no fp32 C write)
template <int EPI>
__global__ __launch_bounds__(256, 2) void gemm_f16(
    const unsigned short* __restrict__ A, int lda,
    const unsigned short* __restrict__ W,        // ldw == K
    const float* __restrict__ bias,
    float* __restrict__ C,
    unsigned short* __restrict__ Ch,
    unsigned short* __restrict__ Xh, int ldc,
    int K,
    const float* __restrict__ P1,
    const float* __restrict__ P2,
    const float* __restrict__ P3,
    const float* __restrict__ a_ptr)
{
    extern __shared__ __align__(16) char smem[];
    const uint32_t sb = (uint32_t)__cvta_generic_to_shared(smem);

    const int t    = threadIdx.x;
    const int lane = t & 31;
    const int warp = t >> 5;
    const int wm   = warp >> 1;      // 0..3
    const int wn   = warp & 1;       // 0..1
    const int m0   = wm * 32;        // warp tile 32x64
    const int n0   = wn * 64;
    const int brow = blockIdx.y * BM;
    const int bcol = blockIdx.x * BN;

    // copy mapping: row = t>>1, k-half = (t&1)*16 elements = segments {2h, 2h+1}
    const int crow = t >> 1;
    const int s0   = (t & 1) * 2;
    const size_t aIdx = (size_t)(brow + crow) * lda + (t & 1) * 16;
    const size_t bIdx = (size_t)(bcol + crow) * K   + (t & 1) * 16;
    const uint32_t d0 = swz(crow, s0);
    const uint32_t d1 = swz(crow, s0 + 1);

    float acc[2][8][4];
#pragma unroll
    for (int mt = 0; mt < 2; mt++)
#pragma unroll
        for (int nt = 0; nt < 8; nt++)
#pragma unroll
            for (int i = 0; i < 4; i++) acc[mt][nt][i] = 0.f;

    const int rA0    = m0 + (lane & 15);
    const int sAbase = lane >> 4;
    const int rB0    = n0 + (lane & 7) + ((lane >> 4) << 3);
    const int sBbase = (lane >> 3) & 1;

    const int nch = K / BK;

    // issue stage 0 (chunk 0)
    {
        cpa16(sb + OFF_A + d0, A + aIdx);
        cpa16(sb + OFF_A + d1, A + aIdx + 8);
        cpa16(sb + OFF_B + d0, W + bIdx);
        cpa16(sb + OFF_B + d1, W + bIdx + 8);
        CPA_COMMIT();
    }

    int stg = 0;
    for (int c = 0; c < nch; c++) {
        if (c + 1 < nch) {
            const int k1 = (c + 1) * BK;
            int stg1 = stg + 1; if (stg1 == NSTG) stg1 = 0;
            const uint32_t sd = sb + (uint32_t)stg1 * SM_STAGE;
            cpa16(sd + OFF_A + d0, A + aIdx + k1);
            cpa16(sd + OFF_A + d1, A + aIdx + k1 + 8);
            cpa16(sd + OFF_B + d0, W + bIdx + k1);
            cpa16(sd + OFF_B + d1, W + bIdx + k1 + 8);
            CPA_COMMIT();
            CPA_WAIT(1);
        } else {
            CPA_WAIT(0);
        }
        __syncthreads();   // single barrier per chunk (ring depth >= 3)

        const uint32_t stgb = sb + (uint32_t)stg * SM_STAGE;
#pragma unroll
        for (int kk = 0; kk < BK; kk += 16) {
            const int sA = sAbase + (kk >> 3);
            const int sB = sBbase + (kk >> 3);
            uint32_t b[4][4];
#pragma unroll
            for (int g = 0; g < 4; g++)
                ldsm_x4(b[g][0], b[g][1], b[g][2], b[g][3],
                        stgb + OFF_B + swz(rB0 + g * 16, sB));
            uint32_t a[2][4];
#pragma unroll
            for (int mt = 0; mt < 2; mt++)
                ldsm_x4(a[mt][0], a[mt][1], a[mt][2], a[mt][3],
                        stgb + OFF_A + swz(rA0 + mt * 16, sA));
#pragma unroll
            for (int mt = 0; mt < 2; mt++)
#pragma unroll
                for (int nt = 0; nt < 8; nt++)
                    mma16816(acc[mt][nt], a[mt],
                             b[nt >> 1][(nt & 1) * 2], b[nt >> 1][(nt & 1) * 2 + 1]);
        }
        if (++stg == NSTG) stg = 0;
    }

    // ---- epilogue ----
    const float alpha = (EPI == 3) ? a_ptr[0] : 0.f;
#pragma unroll
    for (int mt = 0; mt < 2; mt++) {
#pragma unroll
        for (int half = 0; half < 2; half++) {
            const int row  = brow + m0 + mt * 16 + (lane >> 2) + half * 8;
            const int col0 = bcol + n0 + (lane & 3) * 2;
            const size_t base = (size_t)row * ldc + col0;
            const float* brow_b = bias + col0;
#pragma unroll
            for (int nt = 0; nt < 8; nt++) {
                float v0 = acc[mt][nt][half * 2 + 0] + brow_b[nt * 8 + 0];
                float v1 = acc[mt][nt][half * 2 + 1] + brow_b[nt * 8 + 1];
                const size_t idx = base + nt * 8;
                if (EPI == 0) {
                    *(float2*)(C + idx) = make_float2(v0, v1);
                }
                if (EPI == 1) {
                    v0 = fmaxf(v0, 0.f); v1 = fmaxf(v1, 0.f);
                    *(float2*)(C + idx) = make_float2(v0, v1);
                }
                if (EPI == 2) {
                    float2 old = *(float2*)(C + idx);
                    *(float2*)(C + idx) = make_float2(old.x + v0, old.y + v1);
                }
                if (EPI == 3) {
                    float2 old = *(float2*)(C + idx);
                    float l0 = (v0 >= 0.f) ? v0 : alpha * v0;
                    float l1 = (v1 >= 0.f) ? v1 : alpha * v1;
                    float q0 = old.x - l0, q1 = old.y - l1;
                    *(float2*)(C + idx) = make_float2(q0, q1);
                    *(uint32_t*)(Ch + idx) = packh2(q0, q1);
                    float2 p1 = *(const float2*)(P1 + idx);
                    *(uint32_t*)(Xh + idx) = packh2(q0 * p1.x, q1 * p1.y);
                }
                if (EPI == 4) {
                    *(uint32_t*)(Ch + idx) = packh2(v0, v1);
                    float2 p1 = *(const float2*)(P1 + idx);
                    float2 p2 = *(const float2*)(P2 + idx);
                    *(uint32_t*)(Xh + idx) =
                        packh2(v0 * (p1.x + p2.x), v1 * (p1.y + p2.y));
                }
                if (EPI == 5) {
                    float h0 = fmaxf(v0, 0.f), h1 = fmaxf(v1, 0.f);
                    float2 p1 = *(const float2*)(P1 + idx);
                    float2 p2 = *(const float2*)(P2 + idx);
                    float2 p3 = *(const float2*)(P3 + idx);
                    *(uint32_t*)(Xh + idx) =
                        packh2((h0 + p1.x + p2.x) * p3.x,
                               (h1 + p1.y + p2.y) * p3.y);
                }
            }
        }
    }
}

// -------------------- converters & elementwise ----------------------------
__global__ __launch_bounds__(256) void k_cvt(const float* __restrict__ in,
                                             unsigned short* __restrict__ h,
                                             int n4)
{
    const int i = blockIdx.x * blockDim.x + threadIdx.x;
    if (i >= n4) return;
    float4 v = ((const float4*)in)[i];
    ((uint2*)h)[i] = make_uint2(packh2(v.x, v.y), packh2(v.z, v.w));
}

// q = (pi/4)*d^2 ; writes q fp32, qh fp16, tbh = fp16(q*rS)
__global__ __launch_bounds__(256) void k_square(const float* __restrict__ x,
                                                const float* __restrict__ rS,
                                                float* __restrict__ q,
                                                unsigned short* __restrict__ qh,
                                                unsigned short* __restrict__ tbh)
{
    const int i = blockIdx.x * blockDim.x + threadIdx.x;
    const int row = i / (FDIM / 4);
    const int c4  = i % (FDIM / 4);
    const float4 d = *(const float4*)(x + (size_t)row * XDIM + HDIM + B0DIM + c4 * 4);
    const float s = 0.78539816339744830962f;
    float4 o;
    o.x = s * d.x * d.x; o.y = s * d.y * d.y;
    o.z = s * d.z * d.z; o.w = s * d.w * d.w;
    const int oi = row * (FDIM / 4) + c4;
    ((float4*)q)[oi] = o;
    ((uint2*)qh)[oi] = make_uint2(packh2(o.x, o.y), packh2(o.z, o.w));
    const float4 r = ((const float4*)rS)[oi];
    ((uint2*)tbh)[oi] = make_uint2(packh2(o.x * r.x, o.y * r.y),
                                   packh2(o.z * r.z, o.w * r.w));
}

// -------------------- driver ----------------------------------------------
extern "C" void kernel_launch(void* const* d_in, const int* in_sizes, int n_in,
                              void* d_out, int out_size)
{
    const float* x      = (const float*)d_in[0];
    const float* W_h0q  = (const float*)d_in[1];
    const float* b_h0q  = (const float*)d_in[2];
    const float* W_sq   = (const float*)d_in[3];
    const float* b_sq   = (const float*)d_in[4];
    const float* W_h0h  = (const float*)d_in[5];
    const float* b_h0h  = (const float*)d_in[6];
    const float* W_S    = (const float*)d_in[7];
    const float* b_S    = (const float*)d_in[8];
    const float* W_q0h  = (const float*)d_in[9];
    const float* b_q0h  = (const float*)d_in[10];
    const float* Wb_Aq  = (const float*)d_in[11];
    const float* bb_Aq  = (const float*)d_in[12];
    const float* Wb_Dh  = (const float*)d_in[13];
    const float* bb_Dh  = (const float*)d_in[14];
    const float* Wb_fh  = (const float*)d_in[15];
    const float* bb_fh  = (const float*)d_in[16];
    const float* Wb_hf  = (const float*)d_in[17];
    const float* bb_hf  = (const float*)d_in[18];
    const float* a_hf   = (const float*)d_in[19];
    const float* Wb_resq= (const float*)d_in[20];
    const float* bb_resq= (const float*)d_in[21];
    const float* W_out  = (const float*)d_in[22];
    const float* b_out  = (const float*)d_in[23];

    float *q, *sumq, *rS, *sumh, *rqh, *Dh;
    cudaGetSymbolAddress((void**)&q,    g_q);
    cudaGetSymbolAddress((void**)&sumq, g_sumq);
    cudaGetSymbolAddress((void**)&rS,   g_rS);
    cudaGetSymbolAddress((void**)&sumh, g_sumh);
    cudaGetSymbolAddress((void**)&rqh,  g_rqh);
    cudaGetSymbolAddress((void**)&Dh,   g_Dh);

    unsigned short *wh, *xh, *qh, *tbh, *tb2h, *aqh, *thh;
    cudaGetSymbolAddress((void**)&wh,   g_wh);
    cudaGetSymbolAddress((void**)&xh,   g_xh);
    cudaGetSymbolAddress((void**)&qh,   g_qh);
    cudaGetSymbolAddress((void**)&tbh,  g_tbh);
    cudaGetSymbolAddress((void**)&tb2h, g_tb2h);
    cudaGetSymbolAddress((void**)&aqh,  g_aqh);
    cudaGetSymbolAddress((void**)&thh,  g_thh);

    cudaFuncSetAttribute(gemm_f16<0>, cudaFuncAttributeMaxDynamicSharedMemorySize, SMEM_TOTAL);
    cudaFuncSetAttribute(gemm_f16<1>, cudaFuncAttributeMaxDynamicSharedMemorySize, SMEM_TOTAL);
    cudaFuncSetAttribute(gemm_f16<2>, cudaFuncAttributeMaxDynamicSharedMemorySize, SMEM_TOTAL);
    cudaFuncSetAttribute(gemm_f16<3>, cudaFuncAttributeMaxDynamicSharedMemorySize, SMEM_TOTAL);
    cudaFuncSetAttribute(gemm_f16<4>, cudaFuncAttributeMaxDynamicSharedMemorySize, SMEM_TOTAL);
    cudaFuncSetAttribute(gemm_f16<5>, cudaFuncAttributeMaxDynamicSharedMemorySize, SMEM_TOTAL);

    // ---- side streams + events (created once; work is identical each call) ----
    static cudaStream_t s1 = nullptr, s2 = nullptr;
    static cudaEvent_t eX = nullptr, eKS, eQ0H, eH0H, eD[5], eE[5];
    if (s1 == nullptr) {
        cudaStreamCreateWithFlags(&s1, cudaStreamNonBlocking);
        cudaStreamCreateWithFlags(&s2, cudaStreamNonBlocking);
        cudaEventCreateWithFlags(&eX,   cudaEventDisableTiming);
        cudaEventCreateWithFlags(&eKS,  cudaEventDisableTiming);
        cudaEventCreateWithFlags(&eQ0H, cudaEventDisableTiming);
        cudaEventCreateWithFlags(&eH0H, cudaEventDisableTiming);
        for (int i = 0; i < 5; i++) {
            cudaEventCreateWithFlags(&eD[i], cudaEventDisableTiming);
            cudaEventCreateWithFlags(&eE[i], cudaEventDisableTiming);
        }
    }
    cudaStream_t s0 = 0;   // legacy/capture stream

    auto CVT = [&](const float* src, unsigned short* dst, int n, cudaStream_t st) {
        const int n4 = n / 4;
        k_cvt<<<(n4 + 255) / 256, 256, 0, st>>>(src, dst, n4);
    };

    const dim3 gF(FDIM / BN, N_ROWS / BM);   // (16, 64)
    const dim3 gH(HDIM / BN, N_ROWS / BM);   // (8, 64)
    const int ewF = (N_ROWS * FDIM / 4) / 256;

    // ---- s0: x conversion (needed by all prologue GEMMs) ----
    CVT(x, xh, NX, s0);
    cudaEventRecord(eX, s0);

    // ---- s1 chain: W_S -> rS -> k_square -> q0h ----
    cudaStreamWaitEvent(s1, eX, 0);
    CVT(W_S,   wh + O_WS,   NW_WS,   s1);
    CVT(W_q0h, wh + O_WQ0H, NW_WQ0H, s1);
    gemm_f16<1><<<gF, 256, SMEM_TOTAL, s1>>>(xh + HDIM + B0DIM, XDIM, wh + O_WS, b_S,
        rS, nullptr, nullptr, FDIM, FDIM, nullptr, nullptr, nullptr, nullptr);
    k_square<<<ewF, 256, 0, s1>>>(x, rS, q, qh, tbh);
    cudaEventRecord(eKS, s1);
    gemm_f16<0><<<gH, 256, SMEM_TOTAL, s1>>>(qh, FDIM, wh + O_WQ0H, b_q0h,
        rqh, nullptr, nullptr, HDIM, FDIM, nullptr, nullptr, nullptr, nullptr);
    cudaEventRecord(eQ0H, s1);

    // ---- s2 chain: h0h -> sumh ----
    cudaStreamWaitEvent(s2, eX, 0);
    CVT(W_h0h, wh + O_WH0H, NW_WH0H, s2);
    gemm_f16<0><<<gH, 256, SMEM_TOTAL, s2>>>(xh + HDIM, XDIM, wh + O_WH0H, b_h0h,
        sumh, nullptr, nullptr, HDIM, B0DIM, nullptr, nullptr, nullptr, nullptr);
    cudaEventRecord(eH0H, s2);

    // ---- s0 chain: remaining CVTs + sumq ----
    CVT(W_h0q,  wh + O_WH0Q,  NW_WH0Q,  s0);
    CVT(W_sq,   wh + O_WSQ,   NW_WSQ,   s0);
    CVT(W_out,  wh + O_WOUT,  NW_WOUT,  s0);
    CVT(Wb_Aq,  wh + O_WAQ,   NW_WAQ,   s0);
    CVT(Wb_Dh,  wh + O_WDH,   NW_WDH,   s0);
    CVT(Wb_fh,  wh + O_WFH,   NW_WFH,   s0);
    CVT(Wb_hf,  wh + O_WHF,   NW_WHF,   s0);
    CVT(Wb_resq,wh + O_WRESQ, NW_WRESQ, s0);
    gemm_f16<0><<<gF, 256, SMEM_TOTAL, s0>>>(xh + HDIM, XDIM, wh + O_WH0Q, b_h0q,
        sumq, nullptr, nullptr, FDIM, B0DIM, nullptr, nullptr, nullptr, nullptr);
    gemm_f16<2><<<gF, 256, SMEM_TOTAL, s0>>>(xh, XDIM, wh + O_WSQ, b_sq,
        sumq, nullptr, nullptr, FDIM, HDIM, nullptr, nullptr, nullptr, nullptr);
    cudaStreamWaitEvent(s0, eKS, 0);   // tbh, q, qh ready

    // ---- 6 unrolled blocks; resq runs on s1 overlapped with next Aq/Dh ----
    for (int nb = 0; nb < NB; nb++) {
        const size_t oAq   = O_WAQ   + (size_t)nb * FDIM * FDIM;
        const size_t oDh   = O_WDH   + (size_t)nb * HDIM * FDIM;
        const size_t oFh   = O_WFH   + (size_t)nb * HDIM * FDIM;
        const size_t oHf   = O_WHF   + (size_t)nb * FDIM * HDIM;
        const size_t oResq = O_WRESQ + (size_t)nb * HDIM * FDIM;
        const float* bAq   = bb_Aq   + (size_t)nb * FDIM;
        const float* bDh   = bb_Dh   + (size_t)nb * HDIM;
        const float* bfh   = bb_fh   + (size_t)nb * HDIM;
        const float* bhf   = bb_hf   + (size_t)nb * FDIM;
        const float* bresq = bb_resq + (size_t)nb * HDIM;

        // A: A_q = tbh @ W_Aq^T + b ; aqh ; tb2h = fp16(A_q*(q+sumq))
        gemm_f16<4><<<gF, 256, SMEM_TOTAL, s0>>>(tbh, FDIM, wh + oAq, bAq,
            nullptr, aqh, tb2h, FDIM, FDIM, q, sumq, nullptr, nullptr);
        // B: D_h = relu(aqh @ W_Dh^T + b)
        gemm_f16<1><<<gH, 256, SMEM_TOTAL, s0>>>(aqh, FDIM, wh + oDh, bDh,
            Dh, nullptr, nullptr, HDIM, FDIM, nullptr, nullptr, nullptr, nullptr);
        // join rqh producer before C
        if (nb == 0) {
            cudaStreamWaitEvent(s0, eQ0H, 0);
            cudaStreamWaitEvent(s0, eH0H, 0);
        } else {
            cudaStreamWaitEvent(s0, eE[nb - 1], 0);
        }
        // C: h = relu(tb2h @ W_fh^T + b) ; thh = fp16((h+sumh+rqh)*Dh)
        gemm_f16<5><<<gH, 256, SMEM_TOTAL, s0>>>(tb2h, FDIM, wh + oFh, bfh,
            nullptr, nullptr, thh, HDIM, FDIM, sumh, rqh, Dh, nullptr);
        // D: q = q - leaky(thh @ W_hf^T + b) ; qh ; tbh = fp16(q*rS)
        gemm_f16<3><<<gF, 256, SMEM_TOTAL, s0>>>(thh, HDIM, wh + oHf, bhf,
            q, qh, tbh, FDIM, HDIM, rS, nullptr, nullptr, a_hf + nb);
        // E: res_q_h = relu(qh @ W_resq^T + b)  -- on s1, overlapped; skipped
        // for the final block (its result is never consumed).
        if (nb < NB - 1) {
            cudaEventRecord(eD[nb], s0);
            cudaStreamWaitEvent(s1, eD[nb], 0);
            gemm_f16<1><<<gH, 256, SMEM_TOTAL, s1>>>(qh, FDIM, wh + oResq, bresq,
                rqh, nullptr, nullptr, HDIM, FDIM, nullptr, nullptr, nullptr, nullptr);
            cudaEventRecord(eE[nb], s1);
        }
    }

    // ---- output (s0; depends only on qh from final D) ----
    gemm_f16<0><<<gF, 256, SMEM_TOTAL, s0>>>(qh, FDIM, wh + O_WOUT, b_out,
        (float*)d_out, nullptr, nullptr, ODIM, FDIM, nullptr, nullptr, nullptr, nullptr);
}